// round 12
// baseline (speedup 1.0000x reference)
#include <cuda_runtime.h>
#include <cuda_fp16.h>
#include <cstdint>

#define BB 16
#define HH 128
#define WW 128
#define CC 256
#define KK 32
#define NPIX (HH*WW)
#define NCLS 21
#define BN_EPS 1e-3f

// ---------------- kernel A (GEMM1 + softmax) config ----------------
#define A_TPB 768
#define A_GRID 148
#define A_TILE 128
#define A_TILES (BB*NPIX/A_TILE)      // 2048
// smem (bytes)
#define A_XH0 0                        // xhi(par) = par*A_XPAR, pitch 528
#define A_XPAR 67584                   // 128*528
#define A_CWO 135168                   // 32*528 = 16896
#define A_WTS 152064                   // plane*8704, pitch 272, 32 rows
#define A_X2  169472                   // par*512 (128 floats)
#define A_SMEM 170496

// ---------------- kernel B (aggregation GEMM) config ----------------
#define B_TPB 256
#define B_GRID 296
#define B_TILE 32
#define B_TILES (BB*NPIX/B_TILE)      // 8192
// smem (bytes)
#define B_XH0 0                        // par*B_XPAR: xhi 16896 + xlo 16896
#define B_XPAR 33792
#define B_WB  67584                    // par*9216: whi 4608 (pitch 144) + wlo 4608
#define B_SMEM 86016

// ---------------- scratch ----------------
__device__ float g_agg[BB*KK*CC];
__device__ float g_wsum[BB*KK];
__device__ float g_attn[BB*CC];
__device__ float g_c2[KK];
// w planes: [A-tile 2048][plane 2][k 32][p 128] fp16
__device__ __half w_g[2048*2*32*128];

// ---------------- helpers ----------------
__device__ __forceinline__ uint32_t smem_u32(const void* p){
    uint32_t a;
    asm("{ .reg .u64 t; cvta.to.shared.u64 t, %1; cvt.u32.u64 %0, t; }" : "=r"(a) : "l"(p));
    return a;
}
__device__ __forceinline__ void ldsm4(uint32_t* r, uint32_t addr){
    asm volatile("ldmatrix.sync.aligned.m8n8.x4.shared.b16 {%0,%1,%2,%3}, [%4];"
        : "=r"(r[0]),"=r"(r[1]),"=r"(r[2]),"=r"(r[3]) : "r"(addr));
}
__device__ __forceinline__ void ldsm4t(uint32_t* r, uint32_t addr){
    asm volatile("ldmatrix.sync.aligned.m8n8.x4.trans.shared.b16 {%0,%1,%2,%3}, [%4];"
        : "=r"(r[0]),"=r"(r[1]),"=r"(r[2]),"=r"(r[3]) : "r"(addr));
}
__device__ __forceinline__ void mmah(float* d,
    const uint32_t* a, uint32_t b0, uint32_t b1){
    asm volatile("mma.sync.aligned.m16n8k16.row.col.f32.f16.f16.f32 "
        "{%0,%1,%2,%3}, {%4,%5,%6,%7}, {%8,%9}, {%0,%1,%2,%3};"
        : "+f"(d[0]),"+f"(d[1]),"+f"(d[2]),"+f"(d[3])
        : "r"(a[0]),"r"(a[1]),"r"(a[2]),"r"(a[3]),"r"(b0),"r"(b1));
}
__device__ __forceinline__ uint32_t pack_h2(float a, float b){
    __half2 h = __floats2half2_rn(a, b);
    return *(uint32_t*)&h;
}
__device__ __forceinline__ uint2 hi2h(float4 v){
    return make_uint2(pack_h2(v.x, v.y), pack_h2(v.z, v.w));
}
__device__ __forceinline__ float4 residual_h(float4 v, uint2 h){
    __half2 a = *(__half2*)&h.x;
    __half2 b = *(__half2*)&h.y;
    return make_float4(v.x - __half2float(a.x), v.y - __half2float(a.y),
                       v.z - __half2float(b.x), v.w - __half2float(b.y));
}
// LDG one slot (32 floats) of a tile; slot s: row pA = s>>3, col-chunk j = s&7
__device__ __forceinline__ void ldg_slot(float4* v, const float* __restrict__ x,
                                         long long pix0, int s){
    const int pA = s >> 3, j = s & 7;
    const float* src = x + (size_t)(pix0 + pA)*CC + j*8;
    #pragma unroll
    for (int i2 = 0; i2 < 4; i2++){
        v[2*i2]   = *(const float4*)(src + i2*64);
        v[2*i2+1] = *(const float4*)(src + i2*64 + 4);
    }
}

// ---------------- init ----------------
__global__ void k_init(const float* __restrict__ cw){
    int t = blockIdx.x*blockDim.x + threadIdx.x;
    if (t < BB*KK*CC) g_agg[t] = 0.f;
    int t2 = t - BB*KK*CC;
    if (t2 >= 0 && t2 < BB*KK) g_wsum[t2] = 0.f;
    if (t < KK){
        float s = 0.f;
        #pragma unroll 8
        for (int c = 0; c < CC; c++){ float v = cw[t*CC + c]; s += v*v; }
        g_c2[t] = s;
    }
}

// ---------------- kernel A: GEMM1 + softmax -> w_g ----------------
// convert: xhi only + x2 partial
__device__ __forceinline__ void convertA(char* smem, const float4* v, int par, int s){
    const int pA = s >> 3, j = s & 7;
    char* xh = smem + A_XH0 + par*A_XPAR + pA*528 + j*16;
    float x2v = 0.f;
    #pragma unroll
    for (int i2 = 0; i2 < 4; i2++){
        float4 va = v[2*i2], vb = v[2*i2+1];
        x2v += va.x*va.x + va.y*va.y + va.z*va.z + va.w*va.w;
        x2v += vb.x*vb.x + vb.y*vb.y + vb.z*vb.z + vb.w*vb.w;
        uint2 ha = hi2h(va), hb = hi2h(vb);
        *(uint4*)(xh + i2*128) = make_uint4(ha.x, ha.y, hb.x, hb.y);
    }
    x2v += __shfl_xor_sync(0xffffffffu, x2v, 1);
    x2v += __shfl_xor_sync(0xffffffffu, x2v, 2);
    x2v += __shfl_xor_sync(0xffffffffu, x2v, 4);
    if (j == 0) ((float*)(smem + A_X2 + par*512))[pA] = x2v;
}

__global__ __launch_bounds__(A_TPB, 1) void k_enc1(
    const float* __restrict__ x,
    const float* __restrict__ cw,
    const float* __restrict__ smo)
{
    extern __shared__ char smem[];
    const uint32_t sb = smem_u32(smem);
    const int t = threadIdx.x;
    const int lane = t & 31;
    const int wid  = t >> 5;
    const int g4 = lane >> 2, t4 = lane & 3;

    // cw -> fp16 hi plane (once); threads 0-511
    if (t < 512){
        const int row = t >> 4, seg = t & 15;
        const float4* crow = (const float4*)(cw + row*CC) + seg*4;
        float4 v0 = crow[0], v1 = crow[1], v2 = crow[2], v3 = crow[3];
        uint2 h0 = hi2h(v0), h1 = hi2h(v1), h2 = hi2h(v2), h3 = hi2h(v3);
        char* hdst = smem + A_CWO + row*528 + seg*32;
        ((uint4*)hdst)[0] = make_uint4(h0.x,h0.y,h1.x,h1.y);
        ((uint4*)hdst)[1] = make_uint4(h2.x,h2.y,h3.x,h3.y);
    }

    float c2r[8], smr[8];
    if (wid < 8){
        #pragma unroll
        for (int j = 0; j < 8; j++){
            int k = (j >> 1)*8 + t4*2 + (j & 1);
            c2r[j] = g_c2[k]; smr[j] = smo[k];
        }
    }
    float wsum_acc[8];
    #pragma unroll
    for (int j = 0; j < 8; j++) wsum_acc[j] = 0.f;

    const int t0 = (int)(((long long)blockIdx.x     * A_TILES) / A_GRID);
    const int t1 = (int)(((long long)(blockIdx.x+1) * A_TILES) / A_GRID);

    // GEMM1 mappings (warps 0-7, M=128)
    const uint32_t aoff1 = (uint32_t)(wid*16 + (lane & 15)) * 528 + (uint32_t)((lane >> 4) * 16);
    const uint32_t boff1 = (uint32_t)((lane & 7) + ((lane >> 4) << 3)) * 528
                         + (uint32_t)(((lane >> 3) & 1) * 16);
    const int ct = t - 256;   // converter thread index [0,512)

    // prologue: convert tile t0 (1024 slots / 768 threads)
    {
        float4 v[8];
        ldg_slot(v, x, (long long)t0*A_TILE, t);
        convertA(smem, v, t0 & 1, t);
        if (t < 256){
            ldg_slot(v, x, (long long)t0*A_TILE, t + 768);
            convertA(smem, v, t0 & 1, t + 768);
        }
    }
    __syncthreads();

    for (int tt = t0; tt < t1; tt++){
        const int cur = tt & 1, nxt = cur ^ 1;
        const bool haveNext = (tt + 1 < t1);
        const bool lastOfBatch = (((tt + 1) & 127) == 0) || (tt == t1 - 1);

        if (wid < 8){
            // GEMM1: D[p128][k32] = xhi . cwhi^T
            const uint32_t xhiC = A_XH0 + (uint32_t)cur*A_XPAR;
            float d[4][4];
            #pragma unroll
            for (int i = 0; i < 4; i++)
                #pragma unroll
                for (int j = 0; j < 4; j++) d[i][j] = 0.f;
            #pragma unroll 4
            for (int kt = 0; kt < 16; kt++){
                uint32_t a[4], b0[4], b1[4];
                ldsm4(a,  sb + xhiC + aoff1 + kt*32);
                ldsm4(b0, sb + A_CWO + boff1 + kt*32);
                ldsm4(b1, sb + A_CWO + boff1 + 16*528 + kt*32);
                mmah(d[0], a, b0[0], b0[1]);
                mmah(d[1], a, b0[2], b0[3]);
                mmah(d[2], a, b1[0], b1[1]);
                mmah(d[3], a, b1[2], b1[3]);
            }
            // softmax from fragments
            const int px0 = wid*16 + g4, px1 = px0 + 8;
            const float* x2p = (const float*)(smem + A_X2 + cur*512);
            const float xa = x2p[px0], xb = x2p[px1];
            float ea[8], eb[8];
            float mxa = -1e30f, mxb = -1e30f;
            #pragma unroll
            for (int j = 0; j < 8; j++){
                int nt = j >> 1, i = j & 1;
                float la = (xa - 2.f*d[nt][i]     + c2r[j]) * smr[j];
                float lb = (xb - 2.f*d[nt][2 + i] + c2r[j]) * smr[j];
                ea[j] = la; eb[j] = lb;
                mxa = fmaxf(mxa, la); mxb = fmaxf(mxb, lb);
            }
            mxa = fmaxf(mxa, __shfl_xor_sync(0xffffffffu, mxa, 1));
            mxa = fmaxf(mxa, __shfl_xor_sync(0xffffffffu, mxa, 2));
            mxb = fmaxf(mxb, __shfl_xor_sync(0xffffffffu, mxb, 1));
            mxb = fmaxf(mxb, __shfl_xor_sync(0xffffffffu, mxb, 2));
            float sa = 0.f, sbv = 0.f;
            #pragma unroll
            for (int j = 0; j < 8; j++){
                ea[j] = __expf(ea[j] - mxa); sa  += ea[j];
                eb[j] = __expf(eb[j] - mxb); sbv += eb[j];
            }
            sa  += __shfl_xor_sync(0xffffffffu, sa, 1);
            sa  += __shfl_xor_sync(0xffffffffu, sa, 2);
            sbv += __shfl_xor_sync(0xffffffffu, sbv, 1);
            sbv += __shfl_xor_sync(0xffffffffu, sbv, 2);
            const float inva = 1.f / sa, invb = 1.f / sbv;
            char* wh = smem + A_WTS;
            char* wl = wh + 8704;
            #pragma unroll
            for (int j = 0; j < 8; j++){
                int k = (j >> 1)*8 + t4*2 + (j & 1);
                float wa = ea[j]*inva, wb = eb[j]*invb;
                wsum_acc[j] += wa + wb;
                __half ha = __float2half_rn(wa);
                __half hb = __float2half_rn(wb);
                *(__half*)(wh + k*272 + px0*2) = ha;
                *(__half*)(wh + k*272 + px1*2) = hb;
                *(__half*)(wl + k*272 + px0*2) = __float2half_rn(wa - __half2float(ha));
                *(__half*)(wl + k*272 + px1*2) = __float2half_rn(wb - __half2float(hb));
            }
            asm volatile("bar.sync 2, 256;" ::: "memory");
            // coalesced flush wT -> w_g[tt]
            {
                const int r = t >> 2, seg = t & 3;   // t<256 here
                const char* srcp = smem + A_WTS + (r >> 5)*8704 + (r & 31)*272 + seg*64;
                char* dstp = (char*)w_g + (size_t)tt*16384 + r*256 + seg*64;
                uint4 u0 = ((const uint4*)srcp)[0];
                uint4 u1 = ((const uint4*)srcp)[1];
                uint4 u2 = ((const uint4*)srcp)[2];
                uint4 u3 = ((const uint4*)srcp)[3];
                ((uint4*)dstp)[0] = u0; ((uint4*)dstp)[1] = u1;
                ((uint4*)dstp)[2] = u2; ((uint4*)dstp)[3] = u3;
            }
            if (lastOfBatch){
                const int bp = tt >> 7;
                float red[8];
                #pragma unroll
                for (int j = 0; j < 8; j++){
                    float s = wsum_acc[j];
                    s += __shfl_xor_sync(0xffffffffu, s, 4);
                    s += __shfl_xor_sync(0xffffffffu, s, 8);
                    s += __shfl_xor_sync(0xffffffffu, s, 16);
                    red[j] = s; wsum_acc[j] = 0.f;
                }
                if (g4 == 0){
                    #pragma unroll
                    for (int j = 0; j < 8; j++){
                        int k = (j >> 1)*8 + t4*2 + (j & 1);
                        atomicAdd(&g_wsum[bp*KK + k], red[j]);
                    }
                }
            }
        } else if (haveNext){
            // converters: 512 threads x 2 slots
            float4 v[8];
            ldg_slot(v, x, (long long)(tt+1)*A_TILE, ct);
            convertA(smem, v, nxt, ct);
            ldg_slot(v, x, (long long)(tt+1)*A_TILE, ct + 512);
            convertA(smem, v, nxt, ct + 512);
        }
        __syncthreads();
    }
}

// ---------------- kernel B: aggregation GEMM ----------------
__device__ __forceinline__ void convertB(char* smem, const float4* v, int par, int s){
    const int pA = s >> 3, j = s & 7;
    char* xh = smem + B_XH0 + par*B_XPAR + pA*528 + j*16;
    char* xl = xh + 16896;
    #pragma unroll
    for (int i2 = 0; i2 < 4; i2++){
        float4 va = v[2*i2], vb = v[2*i2+1];
        uint2 ha = hi2h(va), hb = hi2h(vb);
        uint2 la = hi2h(residual_h(va, ha)), lb = hi2h(residual_h(vb, hb));
        *(uint4*)(xh + i2*128) = make_uint4(ha.x, ha.y, hb.x, hb.y);
        *(uint4*)(xl + i2*128) = make_uint4(la.x, la.y, lb.x, lb.y);
    }
}

__global__ __launch_bounds__(B_TPB, 2) void k_enc2(const float* __restrict__ x)
{
    extern __shared__ char smem[];
    const uint32_t sb = smem_u32(smem);
    const int t = threadIdx.x;
    const int lane = t & 31;
    const int wid  = t >> 5;
    const int g4 = lane >> 2, t4 = lane & 3;

    // warp mapping: mt = k-half, q = c-quarter
    const int mt = wid & 1, q = wid >> 1;
    const uint32_t a2base = (uint32_t)(lane & 15) * 144 + (uint32_t)((lane >> 4) * 16)
                          + (uint32_t)mt * 2304;     // mt*16 rows * 144
    const uint32_t b2base = (uint32_t)(lane & 15) * 528 + (uint32_t)((lane >> 4) * 16);

    // w load mapping (one uint4 per thread)
    const int wplane = t >> 7, wk = (t >> 2) & 31, wseg = t & 3;

    float acc[8][4];
    #pragma unroll
    for (int i = 0; i < 8; i++)
        #pragma unroll
        for (int j = 0; j < 4; j++) acc[i][j] = 0.f;

    const int t0 = (int)(((long long)blockIdx.x     * B_TILES) / B_GRID);
    const int t1 = (int)(((long long)(blockIdx.x+1) * B_TILES) / B_GRID);

    // prologue: fill buffer for tile t0
    {
        float4 v[8];
        ldg_slot(v, x, (long long)t0*B_TILE, t);
        const int tileA = t0 >> 2, ph = t0 & 3;
        const char* wsrc = (const char*)w_g + (size_t)tileA*16384 + wplane*8192
                         + wk*256 + ph*64 + wseg*16;
        uint4 wu = *(const uint4*)wsrc;
        convertB(smem, v, t0 & 1, t);
        *(uint4*)(smem + B_WB + (t0 & 1)*9216 + wplane*4608 + wk*144 + wseg*16) = wu;
    }
    __syncthreads();

    for (int tt = t0; tt < t1; tt++){
        const int cur = tt & 1, nxt = cur ^ 1;
        const bool haveNext = (tt + 1 < t1);
        const bool lastOfBatch = (((tt + 1) & 511) == 0) || (tt == t1 - 1);

        // early loads for tile tt+1
        float4 v[8];
        uint4 wu;
        if (haveNext){
            ldg_slot(v, x, (long long)(tt+1)*B_TILE, t);
            const int tileA = (tt+1) >> 2, ph = (tt+1) & 3;
            const char* wsrc = (const char*)w_g + (size_t)tileA*16384 + wplane*8192
                             + wk*256 + ph*64 + wseg*16;
            wu = *(const uint4*)wsrc;
        }

        // GEMM2(cur): 3 terms, same accumulators
        {
            const uint32_t xh = B_XH0 + (uint32_t)cur*B_XPAR, xlp = xh + 16896;
            const uint32_t whp = B_WB + (uint32_t)cur*9216, wlp = whp + 4608;
            #pragma unroll
            for (int pt = 0; pt < 2; pt++){
                uint32_t ah[4], al[4];
                ldsm4(ah, sb + whp + a2base + pt*32);
                ldsm4(al, sb + wlp + a2base + pt*32);
                #pragma unroll
                for (int hf = 0; hf < 4; hf++){
                    const uint32_t boff = b2base + (uint32_t)pt*16*528
                                        + (uint32_t)(q*64 + hf*16)*2;
                    uint32_t bh[4], bl[4];
                    ldsm4t(bh, sb + xh  + boff);
                    ldsm4t(bl, sb + xlp + boff);
                    mmah(acc[hf*2],   ah, bh[0], bh[1]);
                    mmah(acc[hf*2+1], ah, bh[2], bh[3]);
                    mmah(acc[hf*2],   ah, bl[0], bl[1]);
                    mmah(acc[hf*2+1], ah, bl[2], bl[3]);
                    mmah(acc[hf*2],   al, bh[0], bh[1]);
                    mmah(acc[hf*2+1], al, bh[2], bh[3]);
                }
            }
        }

        // flush at batch end (after GEMM2 of last tile of batch)
        if (lastOfBatch){
            const int bp = tt >> 9;
            #pragma unroll
            for (int hf = 0; hf < 4; hf++)
                #pragma unroll
                for (int nn = 0; nn < 2; nn++){
                    int i = hf*2 + nn;
                    float* base = g_agg + ((size_t)bp*KK + mt*16 + g4)*CC
                                + q*64 + hf*16 + nn*8 + t4*2;
                    atomicAdd(base,            acc[i][0]);
                    atomicAdd(base + 1,        acc[i][1]);
                    atomicAdd(base + 8*CC,     acc[i][2]);
                    atomicAdd(base + 8*CC + 1, acc[i][3]);
                    acc[i][0] = acc[i][1] = acc[i][2] = acc[i][3] = 0.f;
                }
        }

        // store tile tt+1 into [nxt]
        if (haveNext){
            convertB(smem, v, nxt, t);
            *(uint4*)(smem + B_WB + (uint32_t)nxt*9216 + wplane*4608 + wk*144 + wseg*16) = wu;
        }
        __syncthreads();
    }
}

// ---------------- heads ----------------
__global__ void k_heads(
    const float* __restrict__ cw,
    const float* __restrict__ gamma, const float* __restrict__ beta,
    const float* __restrict__ mean,  const float* __restrict__ var,
    const float* __restrict__ Wenc,  const float* __restrict__ benc,
    const float* __restrict__ Wse,   const float* __restrict__ bse,
    float* __restrict__ out)
{
    const int b = blockIdx.x;
    const int c = threadIdx.x;
    __shared__ float enc[CC];

    float acc = 0.f;
    #pragma unroll
    for (int k = 0; k < KK; k++){
        float a  = g_agg[(b*KK + k)*CC + c] - g_wsum[b*KK + k] * cw[k*CC + c];
        float bn = (a - mean[k]) * rsqrtf(var[k] + BN_EPS) * gamma[k] + beta[k];
        acc += fmaxf(bn, 0.f);
    }
    enc[c] = acc;
    __syncthreads();

    float s = benc[c];
    #pragma unroll 8
    for (int i = 0; i < CC; i++) s += enc[i] * Wenc[i*CC + c];
    g_attn[b*CC + c] = 1.f / (1.f + __expf(-s));

    if (c < NCLS){
        float s2 = bse[c];
        #pragma unroll 8
        for (int i = 0; i < CC; i++) s2 += enc[i] * Wse[i*NCLS + c];
        out[(size_t)BB*NPIX*CC + b*NCLS + c] = 1.f / (1.f + __expf(-s2));
    }
}

// ---------------- rescale ----------------
__global__ void k_scale(const float* __restrict__ x, float* __restrict__ out){
    const int F4 = NPIX*CC/4;
    int idx = blockIdx.x*blockDim.x + threadIdx.x;
    int b  = idx / F4;
    int r  = idx - b*F4;
    int c4 = r & 63;
    float4 a = ((const float4*)g_attn)[b*64 + c4];
    float4 v = __ldcs((const float4*)x + idx);
    v.x *= a.x; v.y *= a.y; v.z *= a.z; v.w *= a.w;
    __stcs((float4*)out + idx, v);
}

extern "C" void kernel_launch(void* const* d_in, const int* in_sizes, int n_in,
                              void* d_out, int out_size)
{
    const float* x     = (const float*)d_in[0];
    const float* cw    = (const float*)d_in[1];
    const float* smo   = (const float*)d_in[2];
    const float* gamma = (const float*)d_in[3];
    const float* beta  = (const float*)d_in[4];
    const float* mean  = (const float*)d_in[5];
    const float* var   = (const float*)d_in[6];
    const float* Wenc  = (const float*)d_in[7];
    const float* benc  = (const float*)d_in[8];
    const float* Wse   = (const float*)d_in[9];
    const float* bse   = (const float*)d_in[10];
    float* out = (float*)d_out;

    cudaFuncSetAttribute(k_enc1, cudaFuncAttributeMaxDynamicSharedMemorySize, A_SMEM);
    cudaFuncSetAttribute(k_enc2, cudaFuncAttributeMaxDynamicSharedMemorySize, B_SMEM);

    int init_total = BB*KK*CC + BB*KK;
    k_init<<<(init_total + 255)/256, 256>>>(cw);
    k_enc1<<<A_GRID, A_TPB, A_SMEM>>>(x, cw, smo);
    k_enc2<<<B_GRID, B_TPB, B_SMEM>>>(x);
    k_heads<<<BB, CC>>>(cw, gamma, beta, mean, var, Wenc, benc, Wse, bse, out);
    k_scale<<<(BB*NPIX*CC/4)/256, 256>>>(x, out);
}

// round 13
// speedup vs baseline: 1.2340x; 1.2340x over previous
#include <cuda_runtime.h>
#include <cuda_fp16.h>
#include <cstdint>

#define BB 16
#define HH 128
#define WW 128
#define CC 256
#define KK 32
#define NPIX (HH*WW)
#define NCLS 21
#define BN_EPS 1e-3f

// ---------- encode config (R11) ----------
#define TILE_P 64
#define TPB_ENC 512
#define GRID_ENC 148
#define TILES_TOTAL (BB*(NPIX/TILE_P))   // 4096

#define PX2   528
#define PCW2  528
#define PWT2  144

#define XH0   0
#define XPAR  67584
#define CWO   135168
#define WT0   152064
#define X2O   170496
#define SMEM_ENC 171008

// ---------------- scratch ----------------
__device__ float g_agg[BB*KK*CC];
__device__ float g_wsum[BB*KK];
__device__ float g_attn[BB*CC];
__device__ float g_c2[KK];
__device__ float g_enc[BB*CC];

// ---------------- helpers ----------------
__device__ __forceinline__ uint32_t smem_u32(const void* p){
    uint32_t a;
    asm("{ .reg .u64 t; cvta.to.shared.u64 t, %1; cvt.u32.u64 %0, t; }" : "=r"(a) : "l"(p));
    return a;
}
__device__ __forceinline__ void ldsm4(uint32_t* r, uint32_t addr){
    asm volatile("ldmatrix.sync.aligned.m8n8.x4.shared.b16 {%0,%1,%2,%3}, [%4];"
        : "=r"(r[0]),"=r"(r[1]),"=r"(r[2]),"=r"(r[3]) : "r"(addr));
}
__device__ __forceinline__ void ldsm4t(uint32_t* r, uint32_t addr){
    asm volatile("ldmatrix.sync.aligned.m8n8.x4.trans.shared.b16 {%0,%1,%2,%3}, [%4];"
        : "=r"(r[0]),"=r"(r[1]),"=r"(r[2]),"=r"(r[3]) : "r"(addr));
}
__device__ __forceinline__ void mmah(float* d,
    const uint32_t* a, uint32_t b0, uint32_t b1){
    asm volatile("mma.sync.aligned.m16n8k16.row.col.f32.f16.f16.f32 "
        "{%0,%1,%2,%3}, {%4,%5,%6,%7}, {%8,%9}, {%0,%1,%2,%3};"
        : "+f"(d[0]),"+f"(d[1]),"+f"(d[2]),"+f"(d[3])
        : "r"(a[0]),"r"(a[1]),"r"(a[2]),"r"(a[3]),"r"(b0),"r"(b1));
}
__device__ __forceinline__ uint32_t pack_h2(float a, float b){
    __half2 h = __floats2half2_rn(a, b);
    return *(uint32_t*)&h;
}
__device__ __forceinline__ uint2 hi2h(float4 v){
    return make_uint2(pack_h2(v.x, v.y), pack_h2(v.z, v.w));
}
__device__ __forceinline__ float4 residual_h(float4 v, uint2 h){
    __half2 a = *(__half2*)&h.x;
    __half2 b = *(__half2*)&h.y;
    return make_float4(v.x - __half2float(a.x), v.y - __half2float(a.y),
                       v.z - __half2float(b.x), v.w - __half2float(b.y));
}
__device__ __forceinline__ void ldg_slot(float4* v, const float* __restrict__ x,
                                         int tile, int s){
    const int pA = s >> 3, j = s & 7;
    const float* src = x + ((size_t)(tile*TILE_P + pA))*CC + j*8;
    #pragma unroll
    for (int i2 = 0; i2 < 4; i2++){
        v[2*i2]   = *(const float4*)(src + i2*64);
        v[2*i2+1] = *(const float4*)(src + i2*64 + 4);
    }
}
__device__ __forceinline__ void convert_slot(char* smem, const float4* v, int par, int s){
    const int pA = s >> 3, j = s & 7;
    char* xh = smem + XH0 + par*XPAR + pA*PX2 + j*16;
    char* xl = xh + 33792;
    float x2v = 0.f;
    #pragma unroll
    for (int i2 = 0; i2 < 4; i2++){
        float4 va = v[2*i2], vb = v[2*i2+1];
        x2v += va.x*va.x + va.y*va.y + va.z*va.z + va.w*va.w;
        x2v += vb.x*vb.x + vb.y*vb.y + vb.z*vb.z + vb.w*vb.w;
        uint2 ha = hi2h(va), hb = hi2h(vb);
        uint2 la = hi2h(residual_h(va, ha)), lb = hi2h(residual_h(vb, hb));
        *(uint4*)(xh + i2*128) = make_uint4(ha.x, ha.y, hb.x, hb.y);
        *(uint4*)(xl + i2*128) = make_uint4(la.x, la.y, lb.x, lb.y);
    }
    x2v += __shfl_xor_sync(0xffffffffu, x2v, 1);
    x2v += __shfl_xor_sync(0xffffffffu, x2v, 2);
    x2v += __shfl_xor_sync(0xffffffffu, x2v, 4);
    if (j == 0) ((float*)(smem + X2O + par*256))[pA] = x2v;
}

// ---------------- init (wide) ----------------
__global__ void k_init(const float* __restrict__ cw){
    int t = blockIdx.x*blockDim.x + threadIdx.x;
    // zero g_agg as float4: 32768 elements
    if (t < BB*KK*CC/4) ((float4*)g_agg)[t] = make_float4(0.f,0.f,0.f,0.f);
    if (t < BB*KK) g_wsum[t] = 0.f;
    if (t >= BB*KK*CC/4 && t < BB*KK*CC/4 + KK){
        int k = t - BB*KK*CC/4;
        float s = 0.f;
        #pragma unroll 8
        for (int c = 0; c < CC; c++){ float v = cw[k*CC + c]; s += v*v; }
        g_c2[k] = s;
    }
}

// ---------------- fused encode (R11, verbatim structure) ----------------
__global__ __launch_bounds__(TPB_ENC, 1) void k_encode(
    const float* __restrict__ x,
    const float* __restrict__ cw,
    const float* __restrict__ smo)
{
    extern __shared__ char smem[];
    const uint32_t sb = smem_u32(smem);
    const int t = threadIdx.x;
    const int lane = t & 31;
    const int wid  = t >> 5;
    const int g4 = lane >> 2, t4 = lane & 3;

    {
        const int row = t >> 4, seg = t & 15;
        const float4* crow = (const float4*)(cw + row*CC) + seg*4;
        float4 v0 = crow[0], v1 = crow[1], v2 = crow[2], v3 = crow[3];
        uint2 h0 = hi2h(v0), h1 = hi2h(v1), h2 = hi2h(v2), h3 = hi2h(v3);
        char* hdst = smem + CWO + row*PCW2 + seg*32;
        ((uint4*)hdst)[0] = make_uint4(h0.x,h0.y,h1.x,h1.y);
        ((uint4*)hdst)[1] = make_uint4(h2.x,h2.y,h3.x,h3.y);
    }

    float c2r[8], smr[8];
    if (wid < 4){
        #pragma unroll
        for (int j = 0; j < 8; j++){
            int k = (j >> 1)*8 + t4*2 + (j & 1);
            c2r[j] = g_c2[k]; smr[j] = smo[k];
        }
    }

    float accC[16][4];
    #pragma unroll
    for (int i = 0; i < 16; i++)
        #pragma unroll
        for (int j = 0; j < 4; j++) accC[i][j] = 0.f;
    float wsum_acc[8];
    #pragma unroll
    for (int j = 0; j < 8; j++) wsum_acc[j] = 0.f;

    const int t0 = (int)(((long long)blockIdx.x     * TILES_TOTAL) / GRID_ENC);
    const int t1 = (int)(((long long)(blockIdx.x+1) * TILES_TOTAL) / GRID_ENC);

    const uint32_t aoff1 = (uint32_t)(wid*16 + (lane & 15)) * PX2 + (uint32_t)((lane >> 4) * 16);
    const uint32_t boff1 = (uint32_t)((lane & 7) + ((lane >> 4) << 3)) * PCW2
                         + (uint32_t)(((lane >> 3) & 1) * 16);
    const int wc = wid - 4;
    const int s2 = wc >> 2, q = wc & 3;
    const uint32_t a2base = (uint32_t)(lane & 15) * PWT2 + (uint32_t)((lane >> 4) * 16);
    const uint32_t b2base = (uint32_t)(lane & 15) * PX2 + (uint32_t)((lane >> 4) * 16);
    const int ct = t - 128;

    {
        float4 v[8];
        ldg_slot(v, x, t0, t);
        convert_slot(smem, v, t0 & 1, t);
    }
    __syncthreads();

    for (int tt = t0; tt < t1; tt++){
        const int cur = tt & 1, nxt = cur ^ 1;
        const bool haveNext = (tt + 1 < t1);
        const bool boundary = (tt > t0) && ((tt >> 8) != ((tt - 1) >> 8));
        const int bp = (tt - 1) >> 8;

        if (wid < 4){
            if (boundary){
                float red[8];
                #pragma unroll
                for (int j = 0; j < 8; j++){
                    float s = wsum_acc[j];
                    s += __shfl_xor_sync(0xffffffffu, s, 4);
                    s += __shfl_xor_sync(0xffffffffu, s, 8);
                    s += __shfl_xor_sync(0xffffffffu, s, 16);
                    red[j] = s; wsum_acc[j] = 0.f;
                }
                if (g4 == 0){
                    #pragma unroll
                    for (int j = 0; j < 8; j++){
                        int k = (j >> 1)*8 + t4*2 + (j & 1);
                        atomicAdd(&g_wsum[bp*KK + k], red[j]);
                    }
                }
            }
            const uint32_t xhiC = XH0 + (uint32_t)cur*XPAR;
            float d[4][4];
            #pragma unroll
            for (int i = 0; i < 4; i++)
                #pragma unroll
                for (int j = 0; j < 4; j++) d[i][j] = 0.f;
            #pragma unroll 4
            for (int kt = 0; kt < 16; kt++){
                uint32_t a[4], b0[4], b1[4];
                ldsm4(a,  sb + xhiC + aoff1 + kt*32);
                ldsm4(b0, sb + CWO + boff1 + kt*32);
                ldsm4(b1, sb + CWO + boff1 + 16*PCW2 + kt*32);
                mmah(d[0], a, b0[0], b0[1]);
                mmah(d[1], a, b0[2], b0[3]);
                mmah(d[2], a, b1[0], b1[1]);
                mmah(d[3], a, b1[2], b1[3]);
            }
            const int px0 = wid*16 + g4, px1 = px0 + 8;
            const float* x2p = (const float*)(smem + X2O + cur*256);
            const float xa = x2p[px0], xb = x2p[px1];
            float ea[8], eb[8];
            float mxa = -1e30f, mxb = -1e30f;
            #pragma unroll
            for (int j = 0; j < 8; j++){
                int nt = j >> 1, i = j & 1;
                float la = (xa - 2.f*d[nt][i]     + c2r[j]) * smr[j];
                float lb = (xb - 2.f*d[nt][2 + i] + c2r[j]) * smr[j];
                ea[j] = la; eb[j] = lb;
                mxa = fmaxf(mxa, la); mxb = fmaxf(mxb, lb);
            }
            mxa = fmaxf(mxa, __shfl_xor_sync(0xffffffffu, mxa, 1));
            mxa = fmaxf(mxa, __shfl_xor_sync(0xffffffffu, mxa, 2));
            mxb = fmaxf(mxb, __shfl_xor_sync(0xffffffffu, mxb, 1));
            mxb = fmaxf(mxb, __shfl_xor_sync(0xffffffffu, mxb, 2));
            float sa = 0.f, sbv = 0.f;
            #pragma unroll
            for (int j = 0; j < 8; j++){
                ea[j] = __expf(ea[j] - mxa); sa  += ea[j];
                eb[j] = __expf(eb[j] - mxb); sbv += eb[j];
            }
            sa  += __shfl_xor_sync(0xffffffffu, sa, 1);
            sa  += __shfl_xor_sync(0xffffffffu, sa, 2);
            sbv += __shfl_xor_sync(0xffffffffu, sbv, 1);
            sbv += __shfl_xor_sync(0xffffffffu, sbv, 2);
            const float inva = 1.f / sa, invb = 1.f / sbv;
            char* wh = smem + WT0 + cur*9216;
            char* wl = wh + 4608;
            #pragma unroll
            for (int j = 0; j < 8; j++){
                int k = (j >> 1)*8 + t4*2 + (j & 1);
                float wa = ea[j]*inva, wb = eb[j]*invb;
                wsum_acc[j] += wa + wb;
                __half ha = __float2half_rn(wa);
                __half hb = __float2half_rn(wb);
                *(__half*)(wh + k*PWT2 + px0*2) = ha;
                *(__half*)(wh + k*PWT2 + px1*2) = hb;
                *(__half*)(wl + k*PWT2 + px0*2) = __float2half_rn(wa - __half2float(ha));
                *(__half*)(wl + k*PWT2 + px1*2) = __float2half_rn(wb - __half2float(hb));
            }
        } else {
            float4 v[8];
            if (haveNext) ldg_slot(v, x, tt + 1, ct);

            if (tt > t0){
                const uint32_t apl = WT0 + (uint32_t)nxt*9216 + (s2 == 2 ? 4608u : 0u);
                const uint32_t bpl = XH0 + (uint32_t)nxt*XPAR + (s2 == 1 ? 33792u : 0u);
                #pragma unroll
                for (int pt = 0; pt < 4; pt++){
                    uint32_t af0[4], af1[4];
                    ldsm4(af0, sb + apl + a2base + pt*32);
                    ldsm4(af1, sb + apl + a2base + 16*PWT2 + pt*32);
                    #pragma unroll
                    for (int hf = 0; hf < 4; hf++){
                        uint32_t bf[4];
                        ldsm4t(bf, sb + bpl + b2base + pt*16*PX2 + (uint32_t)(q*64 + hf*16)*2);
                        mmah(accC[hf*2      ], af0, bf[0], bf[1]);
                        mmah(accC[hf*2 + 1  ], af0, bf[2], bf[3]);
                        mmah(accC[8 + hf*2  ], af1, bf[0], bf[1]);
                        mmah(accC[8 + hf*2+1], af1, bf[2], bf[3]);
                    }
                }
                if (boundary){
                    #pragma unroll
                    for (int mt = 0; mt < 2; mt++)
                        #pragma unroll
                        for (int hf = 0; hf < 4; hf++)
                            #pragma unroll
                            for (int hv = 0; hv < 2; hv++){
                                int i = mt*8 + hf*2 + hv;
                                float* base = g_agg + ((size_t)bp*KK + mt*16 + g4)*CC
                                            + q*64 + hf*16 + hv*8 + t4*2;
                                atomicAdd(base,            accC[i][0]);
                                atomicAdd(base + 1,        accC[i][1]);
                                atomicAdd(base + 8*CC,     accC[i][2]);
                                atomicAdd(base + 8*CC + 1, accC[i][3]);
                                accC[i][0] = accC[i][1] = accC[i][2] = accC[i][3] = 0.f;
                            }
                }
            }
            asm volatile("bar.sync 3, 384;" ::: "memory");
            if (haveNext){
                convert_slot(smem, v, nxt, ct);
                if (ct < 128){
                    float4 v2[8];
                    ldg_slot(v2, x, tt + 1, ct + 384);
                    convert_slot(smem, v2, nxt, ct + 384);
                }
            }
        }
        __syncthreads();
    }

    const int bl2 = (t1 - 1) >> 8;
    if (wid >= 4){
        const int lp = (t1 - 1) & 1;
        const uint32_t apl = WT0 + (uint32_t)lp*9216 + (s2 == 2 ? 4608u : 0u);
        const uint32_t bpl = XH0 + (uint32_t)lp*XPAR + (s2 == 1 ? 33792u : 0u);
        #pragma unroll
        for (int pt = 0; pt < 4; pt++){
            uint32_t af0[4], af1[4];
            ldsm4(af0, sb + apl + a2base + pt*32);
            ldsm4(af1, sb + apl + a2base + 16*PWT2 + pt*32);
            #pragma unroll
            for (int hf = 0; hf < 4; hf++){
                uint32_t bf[4];
                ldsm4t(bf, sb + bpl + b2base + pt*16*PX2 + (uint32_t)(q*64 + hf*16)*2);
                mmah(accC[hf*2      ], af0, bf[0], bf[1]);
                mmah(accC[hf*2 + 1  ], af0, bf[2], bf[3]);
                mmah(accC[8 + hf*2  ], af1, bf[0], bf[1]);
                mmah(accC[8 + hf*2+1], af1, bf[2], bf[3]);
            }
        }
        #pragma unroll
        for (int mt = 0; mt < 2; mt++)
            #pragma unroll
            for (int hf = 0; hf < 4; hf++)
                #pragma unroll
                for (int hv = 0; hv < 2; hv++){
                    int i = mt*8 + hf*2 + hv;
                    float* base = g_agg + ((size_t)bl2*KK + mt*16 + g4)*CC
                                + q*64 + hf*16 + hv*8 + t4*2;
                    atomicAdd(base,            accC[i][0]);
                    atomicAdd(base + 1,        accC[i][1]);
                    atomicAdd(base + 8*CC,     accC[i][2]);
                    atomicAdd(base + 8*CC + 1, accC[i][3]);
                }
    } else {
        float red[8];
        #pragma unroll
        for (int j = 0; j < 8; j++){
            float s = wsum_acc[j];
            s += __shfl_xor_sync(0xffffffffu, s, 4);
            s += __shfl_xor_sync(0xffffffffu, s, 8);
            s += __shfl_xor_sync(0xffffffffu, s, 16);
            red[j] = s;
        }
        if (g4 == 0){
            #pragma unroll
            for (int j = 0; j < 8; j++){
                int k = (j >> 1)*8 + t4*2 + (j & 1);
                atomicAdd(&g_wsum[bl2*KK + k], red[j]);
            }
        }
    }
}

// ---------------- heads (parallelized) ----------------
// enc[b][c] = sum_k relu(bn(agg - wsum*cw))   grid (BB, 8), block 256
__global__ void k_enc_head(
    const float* __restrict__ cw,
    const float* __restrict__ gamma, const float* __restrict__ beta,
    const float* __restrict__ mean,  const float* __restrict__ var)
{
    const int b = blockIdx.x;
    const int c = blockIdx.y*32 + (threadIdx.x & 31);
    const int kq = threadIdx.x >> 5;       // 8 groups of 4 k
    __shared__ float part[8][33];

    float acc = 0.f;
    #pragma unroll
    for (int kk = 0; kk < 4; kk++){
        int k = kq*4 + kk;
        float a  = g_agg[(b*KK + k)*CC + c] - g_wsum[b*KK + k] * cw[k*CC + c];
        float bn = (a - mean[k]) * rsqrtf(var[k] + BN_EPS) * gamma[k] + beta[k];
        acc += fmaxf(bn, 0.f);
    }
    part[kq][threadIdx.x & 31] = acc;
    __syncthreads();
    if (threadIdx.x < 32){
        float s = part[0][threadIdx.x];
        #pragma unroll
        for (int i = 1; i < 8; i++) s += part[i][threadIdx.x];
        g_enc[b*CC + c] = s;
    }
}

// attn + SE: grid (BB, 9): gy<8 -> 32 attn cols; gy==8 -> 21 SE cols
__global__ void k_attn(
    const float* __restrict__ Wenc,  const float* __restrict__ benc,
    const float* __restrict__ Wse,   const float* __restrict__ bse,
    float* __restrict__ out)
{
    const int b = blockIdx.x;
    const int gy = blockIdx.y;
    const int lane = threadIdx.x & 31;
    const int w = threadIdx.x >> 5;        // i-split: 8 groups of 32
    __shared__ float enc_s[CC];
    __shared__ float part[8][33];

    if (threadIdx.x < CC) enc_s[threadIdx.x] = g_enc[b*CC + threadIdx.x];
    __syncthreads();

    if (gy < 8){
        const int c = gy*32 + lane;
        float s = 0.f;
        #pragma unroll 8
        for (int i = 0; i < 32; i++)
            s += enc_s[w*32 + i] * Wenc[(w*32 + i)*CC + c];
        part[w][lane] = s;
        __syncthreads();
        if (threadIdx.x < 32){
            float acc = benc[c - lane + threadIdx.x];
            #pragma unroll
            for (int i = 0; i < 8; i++) acc += part[i][threadIdx.x];
            g_attn[b*CC + gy*32 + threadIdx.x] = 1.f / (1.f + __expf(-acc));
        }
    } else {
        const int c = lane;                // 0..31, valid < NCLS
        float s = 0.f;
        if (c < NCLS){
            #pragma unroll 8
            for (int i = 0; i < 32; i++)
                s += enc_s[w*32 + i] * Wse[(w*32 + i)*NCLS + c];
        }
        part[w][lane] = s;
        __syncthreads();
        if (threadIdx.x < NCLS){
            float acc = bse[threadIdx.x];
            #pragma unroll
            for (int i = 0; i < 8; i++) acc += part[i][threadIdx.x];
            out[(size_t)BB*NPIX*CC + b*NCLS + threadIdx.x] = 1.f / (1.f + __expf(-acc));
        }
    }
}

// ---------------- rescale ----------------
__global__ void k_scale(const float* __restrict__ x, float* __restrict__ out){
    const int F4 = NPIX*CC/4;
    int idx = blockIdx.x*blockDim.x + threadIdx.x;
    int b  = idx / F4;
    int r  = idx - b*F4;
    int c4 = r & 63;
    float4 a = ((const float4*)g_attn)[b*64 + c4];
    float4 v = __ldcs((const float4*)x + idx);
    v.x *= a.x; v.y *= a.y; v.z *= a.z; v.w *= a.w;
    __stcs((float4*)out + idx, v);
}

extern "C" void kernel_launch(void* const* d_in, const int* in_sizes, int n_in,
                              void* d_out, int out_size)
{
    const float* x     = (const float*)d_in[0];
    const float* cw    = (const float*)d_in[1];
    const float* smo   = (const float*)d_in[2];
    const float* gamma = (const float*)d_in[3];
    const float* beta  = (const float*)d_in[4];
    const float* mean  = (const float*)d_in[5];
    const float* var   = (const float*)d_in[6];
    const float* Wenc  = (const float*)d_in[7];
    const float* benc  = (const float*)d_in[8];
    const float* Wse   = (const float*)d_in[9];
    const float* bse   = (const float*)d_in[10];
    float* out = (float*)d_out;

    cudaFuncSetAttribute(k_encode, cudaFuncAttributeMaxDynamicSharedMemorySize, SMEM_ENC);

    k_init<<<128, 256>>>(cw);
    k_encode<<<GRID_ENC, TPB_ENC, SMEM_ENC>>>(x, cw, smo);
    k_enc_head<<<dim3(BB, 8), 256>>>(cw, gamma, beta, mean, var);
    k_attn<<<dim3(BB, 9), 256>>>(Wenc, benc, Wse, bse, out);
    k_scale<<<(BB*NPIX*CC/4)/256, 256>>>(x, out);
}

// round 14
// speedup vs baseline: 1.5903x; 1.2887x over previous
#include <cuda_runtime.h>
#include <cuda_fp16.h>
#include <cstdint>

#define BB 16
#define HH 128
#define WW 128
#define CC 256
#define KK 32
#define NPIX (HH*WW)
#define NCLS 21
#define BN_EPS 1e-3f

// ---------- encode config (R11) ----------
#define TILE_P 64
#define TPB_ENC 512
#define GRID_ENC 148
#define TILES_TOTAL (BB*(NPIX/TILE_P))   // 4096

#define PX2   528
#define PCW2  528
#define PWT2  144

#define XH0   0
#define XPAR  67584
#define CWO   135168
#define WT0   152064
#define X2O   170496
#define SMEM_ENC 171008

// ---------------- scratch ----------------
__device__ float g_agg[BB*KK*CC];
__device__ float g_wsum[BB*KK];
__device__ float g_attn[BB*CC];
__device__ float g_c2[KK];
__device__ float g_enc[BB*CC];

// ---------------- helpers ----------------
__device__ __forceinline__ uint32_t smem_u32(const void* p){
    uint32_t a;
    asm("{ .reg .u64 t; cvta.to.shared.u64 t, %1; cvt.u32.u64 %0, t; }" : "=r"(a) : "l"(p));
    return a;
}
__device__ __forceinline__ void ldsm4(uint32_t* r, uint32_t addr){
    asm volatile("ldmatrix.sync.aligned.m8n8.x4.shared.b16 {%0,%1,%2,%3}, [%4];"
        : "=r"(r[0]),"=r"(r[1]),"=r"(r[2]),"=r"(r[3]) : "r"(addr));
}
__device__ __forceinline__ void ldsm4t(uint32_t* r, uint32_t addr){
    asm volatile("ldmatrix.sync.aligned.m8n8.x4.trans.shared.b16 {%0,%1,%2,%3}, [%4];"
        : "=r"(r[0]),"=r"(r[1]),"=r"(r[2]),"=r"(r[3]) : "r"(addr));
}
__device__ __forceinline__ void mmah(float* d,
    const uint32_t* a, uint32_t b0, uint32_t b1){
    asm volatile("mma.sync.aligned.m16n8k16.row.col.f32.f16.f16.f32 "
        "{%0,%1,%2,%3}, {%4,%5,%6,%7}, {%8,%9}, {%0,%1,%2,%3};"
        : "+f"(d[0]),"+f"(d[1]),"+f"(d[2]),"+f"(d[3])
        : "r"(a[0]),"r"(a[1]),"r"(a[2]),"r"(a[3]),"r"(b0),"r"(b1));
}
__device__ __forceinline__ uint32_t pack_h2(float a, float b){
    __half2 h = __floats2half2_rn(a, b);
    return *(uint32_t*)&h;
}
__device__ __forceinline__ uint2 hi2h(float4 v){
    return make_uint2(pack_h2(v.x, v.y), pack_h2(v.z, v.w));
}
__device__ __forceinline__ float4 residual_h(float4 v, uint2 h){
    __half2 a = *(__half2*)&h.x;
    __half2 b = *(__half2*)&h.y;
    return make_float4(v.x - __half2float(a.x), v.y - __half2float(a.y),
                       v.z - __half2float(b.x), v.w - __half2float(b.y));
}
__device__ __forceinline__ void ldg_slot(float4* v, const float* __restrict__ x,
                                         int tile, int s){
    const int pA = s >> 3, j = s & 7;
    const float* src = x + ((size_t)(tile*TILE_P + pA))*CC + j*8;
    #pragma unroll
    for (int i2 = 0; i2 < 4; i2++){
        v[2*i2]   = *(const float4*)(src + i2*64);
        v[2*i2+1] = *(const float4*)(src + i2*64 + 4);
    }
}
__device__ __forceinline__ void convert_slot(char* smem, const float4* v, int par, int s){
    const int pA = s >> 3, j = s & 7;
    char* xh = smem + XH0 + par*XPAR + pA*PX2 + j*16;
    char* xl = xh + 33792;
    float x2v = 0.f;
    #pragma unroll
    for (int i2 = 0; i2 < 4; i2++){
        float4 va = v[2*i2], vb = v[2*i2+1];
        x2v += va.x*va.x + va.y*va.y + va.z*va.z + va.w*va.w;
        x2v += vb.x*vb.x + vb.y*vb.y + vb.z*vb.z + vb.w*vb.w;
        uint2 ha = hi2h(va), hb = hi2h(vb);
        uint2 la = hi2h(residual_h(va, ha)), lb = hi2h(residual_h(vb, hb));
        *(uint4*)(xh + i2*128) = make_uint4(ha.x, ha.y, hb.x, hb.y);
        *(uint4*)(xl + i2*128) = make_uint4(la.x, la.y, lb.x, lb.y);
    }
    x2v += __shfl_xor_sync(0xffffffffu, x2v, 1);
    x2v += __shfl_xor_sync(0xffffffffu, x2v, 2);
    x2v += __shfl_xor_sync(0xffffffffu, x2v, 4);
    if (j == 0) ((float*)(smem + X2O + par*256))[pA] = x2v;
}

// ---------------- init micro-kernels (3 launches so k_encode is launch #4) ----------------
__global__ void k_zero0(){
    int t = blockIdx.x*blockDim.x + threadIdx.x;
    ((float4*)g_agg)[t] = make_float4(0.f,0.f,0.f,0.f);     // first 16384 float4
}
__global__ void k_zero1(){
    int t = blockIdx.x*blockDim.x + threadIdx.x;
    ((float4*)g_agg)[16384 + t] = make_float4(0.f,0.f,0.f,0.f);
    if (t < BB*KK) g_wsum[t] = 0.f;
}
__global__ void k_c2(const float* __restrict__ cw){
    int k = blockIdx.x;           // 32 blocks, 64 threads
    int t = threadIdx.x;
    __shared__ float part[64];
    float v0 = cw[k*CC + t],  v1 = cw[k*CC + t + 64];
    float v2 = cw[k*CC + t + 128], v3 = cw[k*CC + t + 192];
    part[t] = v0*v0 + v1*v1 + v2*v2 + v3*v3;
    __syncthreads();
    if (t < 32){
        float s = part[t] + part[t + 32];
        #pragma unroll
        for (int o = 16; o > 0; o >>= 1) s += __shfl_xor_sync(0xffffffffu, s, o);
        if (t == 0) g_c2[k] = s;
    }
}

// ---------------- fused encode (R11 structure) ----------------
__global__ __launch_bounds__(TPB_ENC, 1) void k_encode(
    const float* __restrict__ x,
    const float* __restrict__ cw,
    const float* __restrict__ smo)
{
    extern __shared__ char smem[];
    const uint32_t sb = smem_u32(smem);
    const int t = threadIdx.x;
    const int lane = t & 31;
    const int wid  = t >> 5;
    const int g4 = lane >> 2, t4 = lane & 3;

    {
        const int row = t >> 4, seg = t & 15;
        const float4* crow = (const float4*)(cw + row*CC) + seg*4;
        float4 v0 = crow[0], v1 = crow[1], v2 = crow[2], v3 = crow[3];
        uint2 h0 = hi2h(v0), h1 = hi2h(v1), h2 = hi2h(v2), h3 = hi2h(v3);
        char* hdst = smem + CWO + row*PCW2 + seg*32;
        ((uint4*)hdst)[0] = make_uint4(h0.x,h0.y,h1.x,h1.y);
        ((uint4*)hdst)[1] = make_uint4(h2.x,h2.y,h3.x,h3.y);
    }

    float c2r[8], smr[8];
    if (wid < 4){
        #pragma unroll
        for (int j = 0; j < 8; j++){
            int k = (j >> 1)*8 + t4*2 + (j & 1);
            c2r[j] = g_c2[k]; smr[j] = smo[k];
        }
    }

    float accC[16][4];
    #pragma unroll
    for (int i = 0; i < 16; i++)
        #pragma unroll
        for (int j = 0; j < 4; j++) accC[i][j] = 0.f;
    float wsum_acc[8];
    #pragma unroll
    for (int j = 0; j < 8; j++) wsum_acc[j] = 0.f;

    const int t0 = (int)(((long long)blockIdx.x     * TILES_TOTAL) / GRID_ENC);
    const int t1 = (int)(((long long)(blockIdx.x+1) * TILES_TOTAL) / GRID_ENC);

    const uint32_t aoff1 = (uint32_t)(wid*16 + (lane & 15)) * PX2 + (uint32_t)((lane >> 4) * 16);
    const uint32_t boff1 = (uint32_t)((lane & 7) + ((lane >> 4) << 3)) * PCW2
                         + (uint32_t)(((lane >> 3) & 1) * 16);
    const int wc = wid - 4;
    const int s2 = wc >> 2, q = wc & 3;
    const uint32_t a2base = (uint32_t)(lane & 15) * PWT2 + (uint32_t)((lane >> 4) * 16);
    const uint32_t b2base = (uint32_t)(lane & 15) * PX2 + (uint32_t)((lane >> 4) * 16);
    const int ct = t - 128;

    {
        float4 v[8];
        ldg_slot(v, x, t0, t);
        convert_slot(smem, v, t0 & 1, t);
    }
    __syncthreads();

    for (int tt = t0; tt < t1; tt++){
        const int cur = tt & 1, nxt = cur ^ 1;
        const bool haveNext = (tt + 1 < t1);
        const bool boundary = (tt > t0) && ((tt >> 8) != ((tt - 1) >> 8));
        const int bp = (tt - 1) >> 8;

        if (wid < 4){
            if (boundary){
                float red[8];
                #pragma unroll
                for (int j = 0; j < 8; j++){
                    float s = wsum_acc[j];
                    s += __shfl_xor_sync(0xffffffffu, s, 4);
                    s += __shfl_xor_sync(0xffffffffu, s, 8);
                    s += __shfl_xor_sync(0xffffffffu, s, 16);
                    red[j] = s; wsum_acc[j] = 0.f;
                }
                if (g4 == 0){
                    #pragma unroll
                    for (int j = 0; j < 8; j++){
                        int k = (j >> 1)*8 + t4*2 + (j & 1);
                        atomicAdd(&g_wsum[bp*KK + k], red[j]);
                    }
                }
            }
            const uint32_t xhiC = XH0 + (uint32_t)cur*XPAR;
            float d[4][4];
            #pragma unroll
            for (int i = 0; i < 4; i++)
                #pragma unroll
                for (int j = 0; j < 4; j++) d[i][j] = 0.f;
            #pragma unroll 4
            for (int kt = 0; kt < 16; kt++){
                uint32_t a[4], b0[4], b1[4];
                ldsm4(a,  sb + xhiC + aoff1 + kt*32);
                ldsm4(b0, sb + CWO + boff1 + kt*32);
                ldsm4(b1, sb + CWO + boff1 + 16*PCW2 + kt*32);
                mmah(d[0], a, b0[0], b0[1]);
                mmah(d[1], a, b0[2], b0[3]);
                mmah(d[2], a, b1[0], b1[1]);
                mmah(d[3], a, b1[2], b1[3]);
            }
            const int px0 = wid*16 + g4, px1 = px0 + 8;
            const float* x2p = (const float*)(smem + X2O + cur*256);
            const float xa = x2p[px0], xb = x2p[px1];
            float ea[8], eb[8];
            float mxa = -1e30f, mxb = -1e30f;
            #pragma unroll
            for (int j = 0; j < 8; j++){
                int nt = j >> 1, i = j & 1;
                float la = (xa - 2.f*d[nt][i]     + c2r[j]) * smr[j];
                float lb = (xb - 2.f*d[nt][2 + i] + c2r[j]) * smr[j];
                ea[j] = la; eb[j] = lb;
                mxa = fmaxf(mxa, la); mxb = fmaxf(mxb, lb);
            }
            mxa = fmaxf(mxa, __shfl_xor_sync(0xffffffffu, mxa, 1));
            mxa = fmaxf(mxa, __shfl_xor_sync(0xffffffffu, mxa, 2));
            mxb = fmaxf(mxb, __shfl_xor_sync(0xffffffffu, mxb, 1));
            mxb = fmaxf(mxb, __shfl_xor_sync(0xffffffffu, mxb, 2));
            float sa = 0.f, sbv = 0.f;
            #pragma unroll
            for (int j = 0; j < 8; j++){
                ea[j] = __expf(ea[j] - mxa); sa  += ea[j];
                eb[j] = __expf(eb[j] - mxb); sbv += eb[j];
            }
            sa  += __shfl_xor_sync(0xffffffffu, sa, 1);
            sa  += __shfl_xor_sync(0xffffffffu, sa, 2);
            sbv += __shfl_xor_sync(0xffffffffu, sbv, 1);
            sbv += __shfl_xor_sync(0xffffffffu, sbv, 2);
            const float inva = 1.f / sa, invb = 1.f / sbv;
            char* wh = smem + WT0 + cur*9216;
            char* wl = wh + 4608;
            #pragma unroll
            for (int j = 0; j < 8; j++){
                int k = (j >> 1)*8 + t4*2 + (j & 1);
                float wa = ea[j]*inva, wb = eb[j]*invb;
                wsum_acc[j] += wa + wb;
                __half ha = __float2half_rn(wa);
                __half hb = __float2half_rn(wb);
                *(__half*)(wh + k*PWT2 + px0*2) = ha;
                *(__half*)(wh + k*PWT2 + px1*2) = hb;
                *(__half*)(wl + k*PWT2 + px0*2) = __float2half_rn(wa - __half2float(ha));
                *(__half*)(wl + k*PWT2 + px1*2) = __float2half_rn(wb - __half2float(hb));
            }
        } else {
            float4 v[8];
            if (haveNext) ldg_slot(v, x, tt + 1, ct);

            if (tt > t0){
                const uint32_t apl = WT0 + (uint32_t)nxt*9216 + (s2 == 2 ? 4608u : 0u);
                const uint32_t bpl = XH0 + (uint32_t)nxt*XPAR + (s2 == 1 ? 33792u : 0u);
                #pragma unroll
                for (int pt = 0; pt < 4; pt++){
                    uint32_t af0[4], af1[4];
                    ldsm4(af0, sb + apl + a2base + pt*32);
                    ldsm4(af1, sb + apl + a2base + 16*PWT2 + pt*32);
                    #pragma unroll
                    for (int hf = 0; hf < 4; hf++){
                        uint32_t bf[4];
                        ldsm4t(bf, sb + bpl + b2base + pt*16*PX2 + (uint32_t)(q*64 + hf*16)*2);
                        mmah(accC[hf*2      ], af0, bf[0], bf[1]);
                        mmah(accC[hf*2 + 1  ], af0, bf[2], bf[3]);
                        mmah(accC[8 + hf*2  ], af1, bf[0], bf[1]);
                        mmah(accC[8 + hf*2+1], af1, bf[2], bf[3]);
                    }
                }
                if (boundary){
                    #pragma unroll
                    for (int mt = 0; mt < 2; mt++)
                        #pragma unroll
                        for (int hf = 0; hf < 4; hf++)
                            #pragma unroll
                            for (int hv = 0; hv < 2; hv++){
                                int i = mt*8 + hf*2 + hv;
                                float* base = g_agg + ((size_t)bp*KK + mt*16 + g4)*CC
                                            + q*64 + hf*16 + hv*8 + t4*2;
                                atomicAdd(base,            accC[i][0]);
                                atomicAdd(base + 1,        accC[i][1]);
                                atomicAdd(base + 8*CC,     accC[i][2]);
                                atomicAdd(base + 8*CC + 1, accC[i][3]);
                                accC[i][0] = accC[i][1] = accC[i][2] = accC[i][3] = 0.f;
                            }
                }
            }
            asm volatile("bar.sync 3, 384;" ::: "memory");
            if (haveNext){
                convert_slot(smem, v, nxt, ct);
                if (ct < 128){
                    float4 v2[8];
                    ldg_slot(v2, x, tt + 1, ct + 384);
                    convert_slot(smem, v2, nxt, ct + 384);
                }
            }
        }
        __syncthreads();
    }

    const int bl2 = (t1 - 1) >> 8;
    if (wid >= 4){
        const int lp = (t1 - 1) & 1;
        const uint32_t apl = WT0 + (uint32_t)lp*9216 + (s2 == 2 ? 4608u : 0u);
        const uint32_t bpl = XH0 + (uint32_t)lp*XPAR + (s2 == 1 ? 33792u : 0u);
        #pragma unroll
        for (int pt = 0; pt < 4; pt++){
            uint32_t af0[4], af1[4];
            ldsm4(af0, sb + apl + a2base + pt*32);
            ldsm4(af1, sb + apl + a2base + 16*PWT2 + pt*32);
            #pragma unroll
            for (int hf = 0; hf < 4; hf++){
                uint32_t bf[4];
                ldsm4t(bf, sb + bpl + b2base + pt*16*PX2 + (uint32_t)(q*64 + hf*16)*2);
                mmah(accC[hf*2      ], af0, bf[0], bf[1]);
                mmah(accC[hf*2 + 1  ], af0, bf[2], bf[3]);
                mmah(accC[8 + hf*2  ], af1, bf[0], bf[1]);
                mmah(accC[8 + hf*2+1], af1, bf[2], bf[3]);
            }
        }
        #pragma unroll
        for (int mt = 0; mt < 2; mt++)
            #pragma unroll
            for (int hf = 0; hf < 4; hf++)
                #pragma unroll
                for (int hv = 0; hv < 2; hv++){
                    int i = mt*8 + hf*2 + hv;
                    float* base = g_agg + ((size_t)bl2*KK + mt*16 + g4)*CC
                                + q*64 + hf*16 + hv*8 + t4*2;
                    atomicAdd(base,            accC[i][0]);
                    atomicAdd(base + 1,        accC[i][1]);
                    atomicAdd(base + 8*CC,     accC[i][2]);
                    atomicAdd(base + 8*CC + 1, accC[i][3]);
                }
    } else {
        float red[8];
        #pragma unroll
        for (int j = 0; j < 8; j++){
            float s = wsum_acc[j];
            s += __shfl_xor_sync(0xffffffffu, s, 4);
            s += __shfl_xor_sync(0xffffffffu, s, 8);
            s += __shfl_xor_sync(0xffffffffu, s, 16);
            red[j] = s;
        }
        if (g4 == 0){
            #pragma unroll
            for (int j = 0; j < 8; j++){
                int k = (j >> 1)*8 + t4*2 + (j & 1);
                atomicAdd(&g_wsum[bl2*KK + k], red[j]);
            }
        }
    }
}

// ---------------- heads ----------------
__global__ void k_enc_head(
    const float* __restrict__ cw,
    const float* __restrict__ gamma, const float* __restrict__ beta,
    const float* __restrict__ mean,  const float* __restrict__ var)
{
    const int b = blockIdx.x;
    const int c = blockIdx.y*32 + (threadIdx.x & 31);
    const int kq = threadIdx.x >> 5;
    __shared__ float part[8][33];

    float acc = 0.f;
    #pragma unroll
    for (int kk = 0; kk < 4; kk++){
        int k = kq*4 + kk;
        float a  = g_agg[(b*KK + k)*CC + c] - g_wsum[b*KK + k] * cw[k*CC + c];
        float bn = (a - mean[k]) * rsqrtf(var[k] + BN_EPS) * gamma[k] + beta[k];
        acc += fmaxf(bn, 0.f);
    }
    part[kq][threadIdx.x & 31] = acc;
    __syncthreads();
    if (threadIdx.x < 32){
        float s = part[0][threadIdx.x];
        #pragma unroll
        for (int i = 1; i < 8; i++) s += part[i][threadIdx.x];
        g_enc[b*CC + c] = s;
    }
}

__global__ void k_attn(
    const float* __restrict__ Wenc,  const float* __restrict__ benc,
    const float* __restrict__ Wse,   const float* __restrict__ bse,
    float* __restrict__ out)
{
    const int b = blockIdx.x;
    const int gy = blockIdx.y;
    const int lane = threadIdx.x & 31;
    const int w = threadIdx.x >> 5;
    __shared__ float enc_s[CC];
    __shared__ float part[8][33];

    if (threadIdx.x < CC) enc_s[threadIdx.x] = g_enc[b*CC + threadIdx.x];
    __syncthreads();

    if (gy < 8){
        const int c = gy*32 + lane;
        float s = 0.f;
        #pragma unroll 8
        for (int i = 0; i < 32; i++)
            s += enc_s[w*32 + i] * Wenc[(w*32 + i)*CC + c];
        part[w][lane] = s;
        __syncthreads();
        if (threadIdx.x < 32){
            float acc = benc[gy*32 + threadIdx.x];
            #pragma unroll
            for (int i = 0; i < 8; i++) acc += part[i][threadIdx.x];
            g_attn[b*CC + gy*32 + threadIdx.x] = 1.f / (1.f + __expf(-acc));
        }
    } else {
        const int c = lane;
        float s = 0.f;
        if (c < NCLS){
            #pragma unroll 8
            for (int i = 0; i < 32; i++)
                s += enc_s[w*32 + i] * Wse[(w*32 + i)*NCLS + c];
        }
        part[w][lane] = s;
        __syncthreads();
        if (threadIdx.x < NCLS){
            float acc = bse[threadIdx.x];
            #pragma unroll
            for (int i = 0; i < 8; i++) acc += part[i][threadIdx.x];
            out[(size_t)BB*NPIX*CC + b*NCLS + threadIdx.x] = 1.f / (1.f + __expf(-acc));
        }
    }
}

// ---------------- rescale ----------------
__global__ void k_scale(const float* __restrict__ x, float* __restrict__ out){
    const int F4 = NPIX*CC/4;
    int idx = blockIdx.x*blockDim.x + threadIdx.x;
    int b  = idx / F4;
    int r  = idx - b*F4;
    int c4 = r & 63;
    float4 a = ((const float4*)g_attn)[b*64 + c4];
    float4 v = __ldcs((const float4*)x + idx);
    v.x *= a.x; v.y *= a.y; v.z *= a.z; v.w *= a.w;
    __stcs((float4*)out + idx, v);
}

extern "C" void kernel_launch(void* const* d_in, const int* in_sizes, int n_in,
                              void* d_out, int out_size)
{
    const float* x     = (const float*)d_in[0];
    const float* cw    = (const float*)d_in[1];
    const float* smo   = (const float*)d_in[2];
    const float* gamma = (const float*)d_in[3];
    const float* beta  = (const float*)d_in[4];
    const float* mean  = (const float*)d_in[5];
    const float* var   = (const float*)d_in[6];
    const float* Wenc  = (const float*)d_in[7];
    const float* benc  = (const float*)d_in[8];
    const float* Wse   = (const float*)d_in[9];
    const float* bse   = (const float*)d_in[10];
    float* out = (float*)d_out;

    cudaFuncSetAttribute(k_encode, cudaFuncAttributeMaxDynamicSharedMemorySize, SMEM_ENC);

    // launches 1-3: init micro-kernels (so k_encode is launch #4 -> ncu captures it)
    k_zero0<<<64, 256>>>();
    k_zero1<<<64, 256>>>();
    k_c2<<<KK, 64>>>(cw);
    // launch 4: the kernel we need profiled
    k_encode<<<GRID_ENC, TPB_ENC, SMEM_ENC>>>(x, cw, smo);
    k_enc_head<<<dim3(BB, 8), 256>>>(cw, gamma, beta, mean, var);
    k_attn<<<dim3(BB, 9), 256>>>(Wenc, benc, Wse, bse, out);
    k_scale<<<(BB*NPIX*CC/4)/256, 256>>>(x, out);
}